// round 8
// baseline (speedup 1.0000x reference)
#include <cuda_runtime.h>

#define BB 64
#define SS 512
#define KK 7
#define NCHUNK 16
#define NBLK 512          // BB * 8 blocks; each owns 64 rows = 2 chunks

typedef unsigned long long ull;

// scratch (allocation-free rule: __device__ globals)
__device__ float g_M[BB * NCHUNK * 49];  // chunk transfer matrices (log2)
__device__ float g_nump[BB * NCHUNK];    // numerator partials
__device__ int   g_cntp[BB * NCHUNK];    // mask-count partials
__device__ float g_em0[BB * KK];         // emissions row 0 per batch (raw)
__device__ unsigned int g_bcnt[BB];      // per-batch completion (wraps at 8)
__device__ unsigned int g_done = 0;      // batch completion (wraps at 64)
__device__ float g_llh = 0.f;            // llh accumulator (self-resetting)

// ---------------------------------------------------------------------------
__device__ __forceinline__ float ex2f(float x) {
    float y; asm("ex2.approx.f32 %0, %1;" : "=f"(y) : "f"(x)); return y;
}
__device__ __forceinline__ float lg2f(float x) {
    float y; asm("lg2.approx.f32 %0, %1;" : "=f"(y) : "f"(x)); return y;
}
__device__ __forceinline__ ull pk2(float lo, float hi) {
    ull r; asm("mov.b64 %0, {%1,%2};" : "=l"(r) : "f"(lo), "f"(hi)); return r;
}
__device__ __forceinline__ void upk2(ull p, float& lo, float& hi) {
    asm("mov.b64 {%0,%1}, %2;" : "=f"(lo), "=f"(hi) : "l"(p));
}
__device__ __forceinline__ ull fma2(ull a, ull b, ull c) {
    ull d; asm("fma.rn.f32x2 %0, %1, %2, %3;" : "=l"(d) : "l"(a), "l"(b), "l"(c));
    return d;
}

// dtype-width detection (harness may canonicalize bool/int64)
__device__ __forceinline__ int detect_mask_w(const unsigned char* m) {
    unsigned int or123 = 0, or4 = 0;
#pragma unroll
    for (int off = 0; off < 64; off++) {
        unsigned char v = m[off];
        if (off & 3) or123 |= v;
        else if ((off & 7) == 4) or4 |= v;
    }
    if (or123) return 1;
    return or4 ? 4 : 8;
}
__device__ __forceinline__ int detect_gt_w(const void* gt) {
    const int* v = (const int*)gt;
    int orv = 0;
#pragma unroll
    for (int q = 0; q < 64; q++) orv |= v[2 * q + 1];
    return (orv == 0) ? 2 : 1;
}

// ---------------------------------------------------------------------------
// ONE kernel: warps 0-3 stream the GEMV (64 rows); warp 4 consumes emissions
// from smem: chunk transfer matrices + numerator; elected finishers combine.
// ---------------------------------------------------------------------------
__global__ __launch_bounds__(160, 4) void k_one(const float4* __restrict__ x4,
                                                const float* __restrict__ W,
                                                const float* __restrict__ bias,
                                                const void* __restrict__ gt,
                                                const unsigned char* __restrict__ mask,
                                                const float* __restrict__ start_t,
                                                const float* __restrict__ end_t,
                                                const float* __restrict__ trans,
                                                float* __restrict__ out) {
    const int tid = threadIdx.x;
    const int lane = tid & 31, warp = tid >> 5;
    const int g = blockIdx.x;
    const int b = g >> 3, cc = g & 7;
    const long row0 = (long)g * 64;
    const float L2E = 1.4426950408889634f, LN2 = 0.6931471805599453f;

    __shared__ float wsum[4][32][8];
    __shared__ float eexp[2][32][8];
    __shared__ int msk_c[32];

    // ===================== producer state =====================
    ull w01[8], w23[8], w45[8];
    float w6[8];
    float4 buf[2][2];
    // ===================== consumer state =====================
    float Trx[49];
    int mw = 1, gw = 1;

    if (tid < 128) {
        // ---- W slice (56 floats) into registers, packed f32x2 ----
#pragma unroll
        for (int jj = 0; jj < 2; jj++) {
            const float4* wp4 = (const float4*)(W + (tid * 4 + jj * 512) * 7);
            float wb[28];
#pragma unroll
            for (int q4 = 0; q4 < 7; q4++) {
                float4 v = wp4[q4];
                wb[q4 * 4 + 0] = v.x; wb[q4 * 4 + 1] = v.y;
                wb[q4 * 4 + 2] = v.z; wb[q4 * 4 + 3] = v.w;
            }
#pragma unroll
            for (int q = 0; q < 4; q++) {
                int s = jj * 4 + q;
                w01[s] = pk2(wb[q * 7 + 0], wb[q * 7 + 1]);
                w23[s] = pk2(wb[q * 7 + 2], wb[q * 7 + 3]);
                w45[s] = pk2(wb[q * 7 + 4], wb[q * 7 + 5]);
                w6[s] = wb[q * 7 + 6];
            }
        }
        buf[0][0] = __ldcs(&x4[row0 * 256 + tid]);
        buf[0][1] = __ldcs(&x4[row0 * 256 + 128 + tid]);
        buf[1][0] = __ldcs(&x4[(row0 + 1) * 256 + tid]);
        buf[1][1] = __ldcs(&x4[(row0 + 1) * 256 + 128 + tid]);
    } else {
        // consumer prep: widths + exp(trans) in registers
        int mwl = 0, gwl = 0;
        if (lane == 0) { mwl = detect_mask_w(mask); gwl = detect_gt_w(gt); }
        mw = __shfl_sync(0xffffffffu, mwl, 0);
        gw = __shfl_sync(0xffffffffu, gwl, 0);
#pragma unroll
        for (int z = 0; z < 49; z++) Trx[z] = ex2f(trans[z] * L2E);
    }

#define DO_ROW(RR, X0, X1)                                                      \
    {                                                                           \
        float xq[8] = {X0.x, X0.y, X0.z, X0.w, X1.x, X1.y, X1.z, X1.w};         \
        ull c01 = 0, c23 = 0, c45 = 0;                                          \
        float c6 = 0.f;                                                         \
        _Pragma("unroll") for (int s = 0; s < 8; s++) {                         \
            ull xx = pk2(xq[s], xq[s]);                                         \
            c01 = fma2(xx, w01[s], c01);                                        \
            c23 = fma2(xx, w23[s], c23);                                        \
            c45 = fma2(xx, w45[s], c45);                                        \
            c6 = fmaf(xq[s], w6[s], c6);                                        \
        }                                                                       \
        float a[7];                                                             \
        upk2(c01, a[0], a[1]); upk2(c23, a[2], a[3]); upk2(c45, a[4], a[5]);    \
        a[6] = c6;                                                              \
        float tt[7];                                                            \
        _Pragma("unroll") for (int k = 0; k < 7; k++)                           \
            tt[k] = __shfl_xor_sync(0xffffffffu, a[k], 16);                     \
        bool hh = (lane & 16);                                                  \
        float v0 = hh ? a[4] + tt[4] : a[0] + tt[0];                            \
        float v1 = hh ? a[5] + tt[5] : a[1] + tt[1];                            \
        float v2 = hh ? a[6] + tt[6] : a[2] + tt[2];                            \
        float v3 = hh ? 0.f : a[3] + tt[3];                                     \
        float s0 = __shfl_xor_sync(0xffffffffu, v0, 8);                         \
        float s1 = __shfl_xor_sync(0xffffffffu, v1, 8);                         \
        float s2 = __shfl_xor_sync(0xffffffffu, v2, 8);                         \
        float s3 = __shfl_xor_sync(0xffffffffu, v3, 8);                         \
        bool b3p = (lane & 8);                                                  \
        float u0 = b3p ? v2 + s2 : v0 + s0;                                     \
        float u1 = b3p ? v3 + s3 : v1 + s1;                                     \
        float p0 = __shfl_xor_sync(0xffffffffu, u0, 4);                         \
        float p1 = __shfl_xor_sync(0xffffffffu, u1, 4);                         \
        float wv = (lane & 4) ? u1 + p1 : u0 + p0;                              \
        wv += __shfl_xor_sync(0xffffffffu, wv, 2);                              \
        wv += __shfl_xor_sync(0xffffffffu, wv, 1);                              \
        int k7 = (lane >> 2) & 7;                                               \
        if (((lane & 3) == 0) && (k7 < 7)) wsum[warp][(RR) & 31][k7] = wv;      \
    }

#define STREAM_HALF(HALF)                                                       \
    {                                                                           \
        _Pragma("unroll 1") for (int rr = 0; rr < 32; rr += 2) {                \
            _Pragma("unroll") for (int u = 0; u < 2; u++) {                     \
                const int r = (HALF) * 32 + rr + u;                             \
                float4 X0 = buf[u][0], X1 = buf[u][1];                          \
                if (r + 2 < 64) {                                               \
                    buf[u][0] = __ldcs(&x4[(row0 + r + 2) * 256 + tid]);        \
                    buf[u][1] = __ldcs(&x4[(row0 + r + 2) * 256 + 128 + tid]);  \
                }                                                               \
                if (warp == 0 && r + 12 < 64) {                                 \
                    const char* pfp = (const char*)(x4 + (row0 + r + 12) * 256) \
                                      + lane * 128;                             \
                    asm volatile("prefetch.global.L2 [%0];" :: "l"(pfp));       \
                }                                                               \
                DO_ROW(r, X0, X1);                                              \
            }                                                                   \
        }                                                                       \
    }

#define COMBINE_HALF(HALF)                                                      \
    {                                                                           \
        for (int idx = tid; idx < 256; idx += 128) {                            \
            int lt = idx >> 3, k = idx & 7;                                     \
            float e = 1.f;                                                      \
            if (k < 7) {                                                        \
                float raw = wsum[0][lt][k] + wsum[1][lt][k] +                   \
                            wsum[2][lt][k] + wsum[3][lt][k] + bias[k];          \
                e = ex2f(raw * L2E);                                            \
            }                                                                   \
            eexp[HALF][lt][k] = e;                                              \
        }                                                                       \
    }

// consumer: process chunk CH (global within batch) from eexp[HALF]
#define PROCESS_CHUNK(CH, HALF)                                                 \
    {                                                                           \
        const int t_abs0 = (CH) * 32;                                           \
        {   /* stage masks */                                                   \
            int m = mask[((long)b * SS + t_abs0 + lane) * mw] ? 1 : 0;          \
            msk_c[lane] = m;                                                    \
        }                                                                       \
        __syncwarp();                                                           \
        float v[7];                                                             \
        const int i = lane;                                                     \
        _Pragma("unroll") for (int j = 0; j < 7; j++)                           \
            v[j] = (i == j) ? 1.f : 0.f;                                        \
        int mexp = 0;                                                           \
        _Pragma("unroll 1") for (int g4 = 0; g4 < 8; g4++) {                    \
            _Pragma("unroll") for (int q = 0; q < 4; q++) {                     \
                const int lt = g4 * 4 + q;                                      \
                float4 e0 = *(const float4*)&eexp[HALF][lt][0];                 \
                float4 e1 = *(const float4*)&eexp[HALF][lt][4];                 \
                int mk = msk_c[lt];                                             \
                if ((CH) == 0 && lt == 0) mk = 0;                               \
                float nv[7];                                                    \
                _Pragma("unroll") for (int j = 0; j < 7; j++)                   \
                    nv[j] = v[0] * Trx[j];                                      \
                _Pragma("unroll") for (int k = 1; k < 7; k++)                   \
                    _Pragma("unroll") for (int j = 0; j < 7; j++)               \
                        nv[j] = fmaf(v[k], Trx[k * 7 + j], nv[j]);              \
                if (mk) {                                                       \
                    v[0] = nv[0] * e0.x; v[1] = nv[1] * e0.y;                   \
                    v[2] = nv[2] * e0.z; v[3] = nv[3] * e0.w;                   \
                    v[4] = nv[4] * e1.x; v[5] = nv[5] * e1.y;                   \
                    v[6] = nv[6] * e1.z;                                        \
                }                                                               \
            }                                                                   \
            float rs = ((v[0] + v[1]) + (v[2] + v[3])) + ((v[4] + v[5]) + v[6]);\
            int eb = ((__float_as_int(rs) >> 23) & 255) - 127;                  \
            eb = (rs > 0.f) ? eb : 0;                                           \
            float scl = __int_as_float((127 - eb) << 23);                       \
            _Pragma("unroll") for (int j = 0; j < 7; j++) v[j] *= scl;          \
            mexp += eb;                                                         \
        }                                                                       \
        if (i < 7) {                                                            \
            _Pragma("unroll") for (int j = 0; j < 7; j++)                       \
                g_M[(long)(b * NCHUNK + (CH)) * 49 + i * 7 + j] =               \
                    (float)mexp + lg2f(v[j]);                                   \
        }                                                                       \
        /* numerator partial: lane = timestep within chunk */                   \
        {                                                                       \
            const int t_abs = t_abs0 + lane;                                    \
            const int m = msk_c[lane];                                          \
            const int gc = ((const int*)gt)[((long)b * SS + t_abs) * gw];       \
            float emv = lg2f(eexp[HALF][lane][gc]) * LN2;                       \
            float contrib;                                                      \
            if ((CH) == 0 && lane == 0) {                                       \
                contrib = start_t[gc] + emv;                                    \
            } else {                                                            \
                const int gp =                                                  \
                    ((const int*)gt)[((long)b * SS + t_abs - 1) * gw];          \
                contrib = m ? (trans[gp * 7 + gc] + emv) : 0.f;                 \
            }                                                                   \
            float sum = contrib;                                                \
            int cnt = m;                                                        \
            _Pragma("unroll") for (int off = 16; off; off >>= 1) {              \
                sum += __shfl_xor_sync(0xffffffffu, sum, off);                  \
                cnt += __shfl_xor_sync(0xffffffffu, cnt, off);                  \
            }                                                                   \
            if (lane == 0) {                                                    \
                g_nump[b * NCHUNK + (CH)] = sum;                                \
                g_cntp[b * NCHUNK + (CH)] = cnt;                                \
            }                                                                   \
        }                                                                       \
    }

    // ================= barrier ladder =================
    if (tid < 128) STREAM_HALF(0);
    __syncthreads();                       // bar1: wsum(0..31) ready
    if (tid < 128) COMBINE_HALF(0);
    __syncthreads();                       // bar2: eexp[0] ready
    if (tid < 128) {
        STREAM_HALF(1);
    } else {
        // chunk A fully hidden behind half-1 streaming
        PROCESS_CHUNK(cc * 2, 0);
        if (cc == 0 && lane < 7)           // batch row-0 raw emissions
            g_em0[b * 7 + lane] = lg2f(eexp[0][0][lane]) * LN2;
    }
    __syncthreads();                       // bar3: wsum(32..63) ready
    if (tid < 128) COMBINE_HALF(1);
    __syncthreads();                       // bar4: eexp[1] ready
    if (tid < 128) return;                 // producers done

    PROCESS_CHUNK(cc * 2 + 1, 1);          // chunk B (short tail)

    // ---- per-batch finisher election ----
    __threadfence();
    int lastflag = 0;
    if (lane == 0) {
        unsigned int old = atomicInc(&g_bcnt[b], 7u);
        lastflag = (old == 7u) ? 1 : 0;
    }
    lastflag = __shfl_sync(0xffffffffu, lastflag, 0);
    if (!lastflag) return;
    __threadfence();

    // ---- batch combine (one warp) ----
    {
        const int j = lane & 7;
        const int jj = (j < 7) ? j : 0;

        float p = (lane < 16) ? __ldcg(&g_nump[b * 16 + lane]) : 0.f;
        int cn = (lane < 16) ? __ldcg(&g_cntp[b * 16 + lane]) : 0;
#pragma unroll
        for (int off = 16; off; off >>= 1) {
            p += __shfl_xor_sync(0xffffffffu, p, off);
            cn += __shfl_xor_sync(0xffffffffu, cn, off);
        }
        const float num = p + end_t[((const int*)gt)[((long)b * SS + cn - 1) * gw]];

        float a = (j < 7) ? (start_t[jj] + __ldcg(&g_em0[b * 7 + jj])) * L2E : -1e30f;
        float M[7], M2[7];
#pragma unroll
        for (int i2 = 0; i2 < 7; i2++)
            M[i2] = __ldcg(&g_M[(long)(b * 16) * 49 + i2 * 7 + jj]);

        for (int ch = 0; ch < NCHUNK; ch++) {
            if (ch + 1 < NCHUNK) {
#pragma unroll
                for (int i2 = 0; i2 < 7; i2++)
                    M2[i2] = __ldcg(&g_M[(long)(b * 16 + ch + 1) * 49 + i2 * 7 + jj]);
            }
            float mx = -1e30f;
            float vv[7];
#pragma unroll
            for (int i2 = 0; i2 < 7; i2++) {
                vv[i2] = __shfl_sync(0xffffffffu, a, i2, 8) + M[i2];
                mx = fmaxf(mx, vv[i2]);
            }
            float sum = 0.f;
#pragma unroll
            for (int i2 = 0; i2 < 7; i2++) sum += ex2f(vv[i2] - mx);
            float anew = mx + lg2f(sum);
            a = (j < 7) ? anew : -1e30f;
#pragma unroll
            for (int i2 = 0; i2 < 7; i2++) M[i2] = M2[i2];
        }

        float z = (j < 7) ? a + end_t[jj] * L2E : -1e30f;
        float mz = z;
#pragma unroll
        for (int off = 4; off; off >>= 1)
            mz = fmaxf(mz, __shfl_xor_sync(0xffffffffu, mz, off, 8));
        float se = ex2f(z - mz);
#pragma unroll
        for (int off = 4; off; off >>= 1)
            se += __shfl_xor_sync(0xffffffffu, se, off, 8);
        const float denom = (mz + lg2f(se)) * LN2;

        if (lane == 0) {
            atomicAdd(&g_llh, num - denom);
            __threadfence();
            unsigned int old = atomicInc(&g_done, BB - 1);
            if (old == BB - 1) {
                float tot = atomicExch(&g_llh, 0.f);
                out[0] = -tot / (float)BB;
            }
        }
    }
#undef DO_ROW
#undef STREAM_HALF
#undef COMBINE_HALF
#undef PROCESS_CHUNK
}

// ---------------------------------------------------------------------------
extern "C" void kernel_launch(void* const* d_in, const int* in_sizes, int n_in,
                              void* d_out, int out_size) {
    const float4* x = (const float4*)d_in[0];
    const void* gt = d_in[1];
    const unsigned char* mask = (const unsigned char*)d_in[2];
    const float* W = (const float*)d_in[3];
    const float* bias = (const float*)d_in[4];
    const float* start_t = (const float*)d_in[5];
    const float* end_t = (const float*)d_in[6];
    const float* trans = (const float*)d_in[7];
    float* out = (float*)d_out;

    k_one<<<NBLK, 160>>>(x, W, bias, gt, mask, start_t, end_t, trans, out);
}